// round 11
// baseline (speedup 1.0000x reference)
#include <cuda_runtime.h>
#include <cuda_fp16.h>
#include <math.h>
#include <stdint.h>

#define N_FIELDS 8
#define HIDDEN   128
#define GEO      15
#define APP      32
#define CIN      50
#define N_MAX    524288
#define TILE     128
#define TILES_PER_BLOCK 8
#define PTS_PER_BLOCK   1024

#define H_STRIDE   36    // words/row; 36%32=4 -> LDSM conflict-free (144B)
#define WD2_STRIDE 68    // words/row; 68%32=4 (272B)
#define WC1_STRIDE 36    // words/row; n-major (144B)

// ---- dynamic smem layout (32-bit word offsets) ----
#define OFF_WD1    0       // 384
#define OFF_BD1    384     // 128
#define OFF_BD2    512     // 16
#define OFF_BC1    528     // 128
#define OFF_BC2    656     // 4
#define OFF_WC2    660     // 512 (float4[128]); byte 2640, 16B aligned
#define OFF_WD2H   1172    // [16][68] = 1088
#define OFF_WC1    2260    // [128][36] = 4608 ; byte 9040, 16B aligned
#define OFF_H      6868    // [128][36] = 4608 ; byte 27472, 16B aligned
#define SMEM_WORDS 11476
#define SMEM_BYTES (SMEM_WORDS * 4)   // 45904 B

// ---------------- device scratch ----------------
__device__ int g_counts[N_FIELDS];
__device__ int g_bucket[N_FIELDS][N_MAX];

__global__ void k_assign(const float* __restrict__ pos,
                         const float* __restrict__ cent, int n) {
    int i = blockIdx.x * blockDim.x + threadIdx.x;
    unsigned act = __ballot_sync(0xffffffffu, i < n);
    if (i >= n) return;
    float px = pos[3*i], py = pos[3*i+1], pz = pos[3*i+2];
    int best = 0; float bd = 3.402823e38f;
    #pragma unroll
    for (int c = 0; c < N_FIELDS; c++) {
        float dx = px - __ldg(&cent[3*c+0]);
        float dy = py - __ldg(&cent[3*c+1]);
        float dz = pz - __ldg(&cent[3*c+2]);
        float d = dx*dx + dy*dy + dz*dz;
        if (d < bd) { bd = d; best = c; }
    }
    unsigned peers  = __match_any_sync(act, best);
    int leader = __ffs(peers) - 1;
    int lane   = threadIdx.x & 31;
    int base = 0;
    if (lane == leader) base = atomicAdd(&g_counts[best], __popc(peers));
    base = __shfl_sync(peers, base, leader);
    g_bucket[best][base + __popc(peers & ((1u << lane) - 1u))] = i;
}

// ---- helpers ----
__device__ __forceinline__ unsigned packh2(float lo, float hi) {
    __half2 h = __floats2half2_rn(lo, hi);
    return *(unsigned*)&h;
}
__device__ __forceinline__ void mma_f16(float& c0, float& c1, float& c2, float& c3,
                                        unsigned a0, unsigned a1, unsigned a2, unsigned a3,
                                        unsigned b0, unsigned b1) {
    asm("mma.sync.aligned.m16n8k16.row.col.f32.f16.f16.f32 "
        "{%0,%1,%2,%3},{%4,%5,%6,%7},{%8,%9},{%0,%1,%2,%3};"
        : "+f"(c0), "+f"(c1), "+f"(c2), "+f"(c3)
        : "r"(a0), "r"(a1), "r"(a2), "r"(a3), "r"(b0), "r"(b1));
}
__device__ __forceinline__ void ldsm4(unsigned& r0, unsigned& r1,
                                      unsigned& r2, unsigned& r3, uint32_t a) {
    asm volatile("ldmatrix.sync.aligned.m8n8.x4.shared.b16 {%0,%1,%2,%3}, [%4];"
        : "=r"(r0), "=r"(r1), "=r"(r2), "=r"(r3) : "r"(a));
}

// ---------------- kernel 2 ----------------
__global__ void __launch_bounds__(TILE, 4)
k_field(const float* __restrict__ pos, const float* __restrict__ dir,
        const float* __restrict__ app,
        const float* __restrict__ Wd1, const float* __restrict__ bd1,
        const float* __restrict__ Wd2, const float* __restrict__ bd2,
        const float* __restrict__ Wc1, const float* __restrict__ bc1,
        const float* __restrict__ Wc2, const float* __restrict__ bc2,
        float* __restrict__ out, int tpf)
{
    extern __shared__ float sm[];
    unsigned* smw = (unsigned*)sm;

    int f = blockIdx.x / tpf;
    int t = blockIdx.x - f * tpf;
    int cnt = g_counts[f];
    if (t * PTS_PER_BLOCK >= cnt) return;

    int tid = threadIdx.x;

    // ---- stage weights (once per block) ----
    {
        const float* g = Wd1 + f*3*HIDDEN;
        for (int i = tid; i < 3*HIDDEN; i += TILE) sm[OFF_WD1 + i] = g[i];
    }
    sm[OFF_BD1 + tid] = bd1[f*HIDDEN + tid];
    if (tid < 16) sm[OFF_BD2 + tid] = bd2[f*16 + tid];
    sm[OFF_BC1 + tid] = bc1[f*HIDDEN + tid];
    if (tid < 3) sm[OFF_BC2 + tid] = bc2[f*3 + tid];
    if (tid == 3) sm[OFF_BC2 + 3] = 0.f;
    {   // Wd2 [k=128][n=16] -> n-major half2: [n=16][kp=64], stride 68
        const float* g = Wd2 + f*HIDDEN*16;
        for (int i = tid; i < 16*64; i += TILE) {
            int n = i >> 6, kp = i & 63;
            smw[OFF_WD2H + n*WD2_STRIDE + kp] =
                packh2(g[(2*kp)*16 + n], g[(2*kp+1)*16 + n]);
        }
    }
    {   // Wc1 [k=50][n=128] -> n-major half2: [n=128][kp=32], stride 36
        const float* g = Wc1 + f*CIN*HIDDEN;
        for (int i = tid; i < 128*32; i += TILE) {
            int n = i >> 5, kp = i & 31;
            unsigned w = 0u;
            if (kp < 25)
                w = packh2(g[(2*kp)*HIDDEN + n], g[(2*kp+1)*HIDDEN + n]);
            smw[OFF_WC1 + n*WC1_STRIDE + kp] = w;
        }
    }
    {
        const float* g = Wc2 + f*HIDDEN*3;
        sm[OFF_WC2 + tid*4+0] = g[tid*3+0];
        sm[OFF_WC2 + tid*4+1] = g[tid*3+1];
        sm[OFF_WC2 + tid*4+2] = g[tid*3+2];
        sm[OFF_WC2 + tid*4+3] = 0.f;
    }
    __syncthreads();

    int lane = tid & 31;
    int wid  = tid >> 5;
    int g    = lane >> 2;
    int tg   = lane & 3;
    int wbase = wid * 32;
    int lr = lane & 7;      // row within LDSM matrix
    int lm = lane >> 3;     // matrix index 0..3

    uint32_t sb   = (uint32_t)__cvta_generic_to_shared(sm);
    uint32_t Hb   = sb + OFF_H*4;
    uint32_t WC1b = sb + OFF_WC1*4;
    uint32_t WD2b = sb + OFF_WD2H*4;
    const float4* WC2v = (const float4*)(sm + OFF_WC2);

    // LDSM A address (H): per (mtrow, ks): rows mtrow + lr + 8*(lm&1), seg ks*32 + (lm>>1)*16
    #define A_ADDR(mtrow, ks) (Hb + (uint32_t)(((mtrow) + lr + 8*(lm & 1))*144 + (ks)*32 + (lm >> 1)*16))
    // LDSM B address (n-major, strideB bytes): per (n0, kspair): rows n0+lr, seg kspair*64 + lm*16
    #define B_ADDR(basep, n0, strideB, kspair) ((basep) + (uint32_t)(((n0) + lr)*(strideB) + (kspair)*64 + lm*16))

    for (int tile = 0; tile < TILES_PER_BLOCK; tile++) {
        int base = t * PTS_PER_BLOCK + tile * TILE;
        if (base >= cnt) break;
        int bi = base + tid;
        bool valid = (bi < cnt);
        int p = g_bucket[f][valid ? bi : (cnt - 1)];

        float px = pos[3*p], py = pos[3*p+1], pz = pos[3*p+2];
        uint4* hrow = (uint4*)(smw + OFF_H + tid*H_STRIDE);

        float cd[2][2][8];   // [mt][nt][cA0..3, cB0..3]
        #pragma unroll
        for (int mt = 0; mt < 2; mt++)
            #pragma unroll
            for (int nt = 0; nt < 2; nt++)
                #pragma unroll
                for (int q = 0; q < 8; q++) cd[mt][nt][q] = 0.f;

        // ==== two K-halves of the density GEMM, h tile reused in-place ====
        #pragma unroll
        for (int hb = 0; hb < 2; hb++) {
            // ---- L1: h[64*hb .. 64*hb+63] -> H words 0..31 ----
            #pragma unroll
            for (int j = 0; j < 64; j += 8) {
                float hv[8];
                #pragma unroll
                for (int u = 0; u < 8; u++) {
                    int jj = 64*hb + j + u;
                    hv[u] = fmaxf(fmaf(px, sm[OFF_WD1 + 0*HIDDEN + jj],
                                  fmaf(py, sm[OFF_WD1 + 1*HIDDEN + jj],
                                  fmaf(pz, sm[OFF_WD1 + 2*HIDDEN + jj],
                                       sm[OFF_BD1 + jj]))), 0.f);
                }
                hrow[j >> 3] = make_uint4(packh2(hv[0],hv[1]), packh2(hv[2],hv[3]),
                                          packh2(hv[4],hv[5]), packh2(hv[6],hv[7]));
            }
            __syncwarp();

            // ---- A-frags for this half (LDSM) ----
            unsigned a1[2][4][4];
            #pragma unroll
            for (int mt = 0; mt < 2; mt++)
                #pragma unroll
                for (int ks = 0; ks < 4; ks++)
                    ldsm4(a1[mt][ks][0], a1[mt][ks][1], a1[mt][ks][2], a1[mt][ks][3],
                          A_ADDR(wbase + 16*mt, ks));

            // ---- d0 MMA for this half ----
            #pragma unroll
            for (int nt = 0; nt < 2; nt++) {
                unsigned bb[2][4];
                #pragma unroll
                for (int c = 0; c < 2; c++)
                    ldsm4(bb[c][0], bb[c][1], bb[c][2], bb[c][3],
                          B_ADDR(WD2b, 8*nt, 272, 2*hb + c));
                #pragma unroll
                for (int mt = 0; mt < 2; mt++) {
                    float* c = cd[mt][nt];
                    // cA <- local ks 0,2 ; cB <- local ks 1,3 (same chains as R10)
                    mma_f16(c[0],c[1],c[2],c[3],
                            a1[mt][0][0],a1[mt][0][1],a1[mt][0][2],a1[mt][0][3],
                            bb[0][0], bb[0][1]);
                    mma_f16(c[4],c[5],c[6],c[7],
                            a1[mt][1][0],a1[mt][1][1],a1[mt][1][2],a1[mt][1][3],
                            bb[0][2], bb[0][3]);
                    mma_f16(c[0],c[1],c[2],c[3],
                            a1[mt][2][0],a1[mt][2][1],a1[mt][2][2],a1[mt][2][3],
                            bb[1][0], bb[1][1]);
                    mma_f16(c[4],c[5],c[6],c[7],
                            a1[mt][3][0],a1[mt][3][1],a1[mt][3][2],a1[mt][3][3],
                            bb[1][2], bb[1][3]);
                }
            }
            __syncwarp();   // before overwriting H (hb=0) / storing d0 (hb=1)
        }

        // ---- store d0 frags into H words 0..15 of own rows ----
        #pragma unroll
        for (int mt = 0; mt < 2; mt++) {
            int r0 = wbase + 16*mt + g;
            #pragma unroll
            for (int nt = 0; nt < 2; nt++) {
                float* c = cd[mt][nt];
                int cb = 8*nt + 2*tg;
                float* rA = sm + OFF_H + (size_t)(r0    )*H_STRIDE + cb;
                float* rB = sm + OFF_H + (size_t)(r0 + 8)*H_STRIDE + cb;
                rA[0] = c[0] + c[4];  rA[1] = c[1] + c[5];
                rB[0] = c[2] + c[6];  rB[1] = c[3] + c[7];
            }
        }
        __syncwarp();

        // ---- readback d0 (own row), density out, build CIN in-place ----
        {
            float d0[16];
            const float4* drow = (const float4*)(sm + OFF_H + (size_t)tid*H_STRIDE);
            #pragma unroll
            for (int q = 0; q < 4; q++) {
                float4 v = drow[q];
                d0[4*q+0] = v.x + sm[OFF_BD2 + 4*q+0];
                d0[4*q+1] = v.y + sm[OFF_BD2 + 4*q+1];
                d0[4*q+2] = v.z + sm[OFF_BD2 + 4*q+2];
                d0[4*q+3] = v.w + sm[OFF_BD2 + 4*q+3];
            }
            if (valid) out[(size_t)4*p] = expf(d0[0]);

            float cv[56];
            cv[0] = dir[3*p]; cv[1] = dir[3*p+1]; cv[2] = dir[3*p+2];
            #pragma unroll
            for (int g2 = 0; g2 < GEO; g2++) cv[3+g2] = d0[1+g2];
            const float4* ap = (const float4*)(app + (size_t)p*APP);
            #pragma unroll
            for (int q = 0; q < APP/4; q++) {
                float4 v = __ldg(&ap[q]);
                cv[18+4*q+0] = v.x; cv[18+4*q+1] = v.y;
                cv[18+4*q+2] = v.z; cv[18+4*q+3] = v.w;
            }
            #pragma unroll
            for (int c = CIN; c < 56; c++) cv[c] = 0.f;
            #pragma unroll
            for (int q = 0; q < 8; q++) {
                uint4 v;
                v.x = (q < 7) ? packh2(cv[8*q+0], cv[8*q+1]) : 0u;
                v.y = (q < 7) ? packh2(cv[8*q+2], cv[8*q+3]) : 0u;
                v.z = (q < 7) ? packh2(cv[8*q+4], cv[8*q+5]) : 0u;
                v.w = (q < 7) ? packh2(cv[8*q+6], cv[8*q+7]) : 0u;
                hrow[q] = v;
            }
        }
        __syncwarp();

        // ---- color MMA with LDSM + double-buffered B-frags ----
        unsigned a[2][4][4];
        #pragma unroll
        for (int mt = 0; mt < 2; mt++)
            #pragma unroll
            for (int ks = 0; ks < 4; ks++)
                ldsm4(a[mt][ks][0], a[mt][ks][1], a[mt][ks][2], a[mt][ks][3],
                      A_ADDR(wbase + 16*mt, ks));

        float acc[4][3];
        #pragma unroll
        for (int q = 0; q < 4; q++) { acc[q][0]=0.f; acc[q][1]=0.f; acc[q][2]=0.f; }

        unsigned bb[2][8];
        ldsm4(bb[0][0], bb[0][1], bb[0][2], bb[0][3], B_ADDR(WC1b, 0, 144, 0));
        ldsm4(bb[0][4], bb[0][5], bb[0][6], bb[0][7], B_ADDR(WC1b, 0, 144, 1));

        #pragma unroll 2
        for (int nb = 0; nb < 16; nb++) {
            int cur = nb & 1, nxt = cur ^ 1;
            if (nb < 15) {   // prefetch next nb's B-frags
                ldsm4(bb[nxt][0], bb[nxt][1], bb[nxt][2], bb[nxt][3],
                      B_ADDR(WC1b, 8*(nb+1), 144, 0));
                ldsm4(bb[nxt][4], bb[nxt][5], bb[nxt][6], bb[nxt][7],
                      B_ADDR(WC1b, 8*(nb+1), 144, 1));
            }
            int j0 = 8*nb + 2*tg;
            float bj0 = sm[OFF_BC1 + j0], bj1 = sm[OFF_BC1 + j0 + 1];
            float4 w0 = WC2v[j0];
            float4 w1 = WC2v[j0 + 1];

            #pragma unroll
            for (int mt = 0; mt < 2; mt++) {
                float cA0=0.f,cA1=0.f,cA2=0.f,cA3=0.f;
                float cB0=0.f,cB1=0.f,cB2=0.f,cB3=0.f;
                mma_f16(cA0,cA1,cA2,cA3, a[mt][0][0],a[mt][0][1],a[mt][0][2],a[mt][0][3], bb[cur][0],bb[cur][1]);
                mma_f16(cB0,cB1,cB2,cB3, a[mt][1][0],a[mt][1][1],a[mt][1][2],a[mt][1][3], bb[cur][2],bb[cur][3]);
                mma_f16(cA0,cA1,cA2,cA3, a[mt][2][0],a[mt][2][1],a[mt][2][2],a[mt][2][3], bb[cur][4],bb[cur][5]);
                mma_f16(cB0,cB1,cB2,cB3, a[mt][3][0],a[mt][3][1],a[mt][3][2],a[mt][3][3], bb[cur][6],bb[cur][7]);
                float h00 = fmaxf(cA0 + cB0 + bj0, 0.f);
                float h01 = fmaxf(cA1 + cB1 + bj1, 0.f);
                float h10 = fmaxf(cA2 + cB2 + bj0, 0.f);
                float h11 = fmaxf(cA3 + cB3 + bj1, 0.f);
                int q0 = 2*mt, q1 = 2*mt + 1;
                acc[q0][0] = fmaf(h00, w0.x, fmaf(h01, w1.x, acc[q0][0]));
                acc[q0][1] = fmaf(h00, w0.y, fmaf(h01, w1.y, acc[q0][1]));
                acc[q0][2] = fmaf(h00, w0.z, fmaf(h01, w1.z, acc[q0][2]));
                acc[q1][0] = fmaf(h10, w0.x, fmaf(h11, w1.x, acc[q1][0]));
                acc[q1][1] = fmaf(h10, w0.y, fmaf(h11, w1.y, acc[q1][1]));
                acc[q1][2] = fmaf(h10, w0.z, fmaf(h11, w1.z, acc[q1][2]));
            }
        }

        #pragma unroll
        for (int q = 0; q < 4; q++)
            #pragma unroll
            for (int c = 0; c < 3; c++) {
                float v = acc[q][c];
                v += __shfl_xor_sync(0xffffffffu, v, 1);
                v += __shfl_xor_sync(0xffffffffu, v, 2);
                acc[q][c] = v;
            }

        {
            int row = wbase + g + 8*tg;
            int bi2 = base + row;
            if (bi2 < cnt) {
                int pp = g_bucket[f][bi2];
                float r0 = acc[tg][0] + sm[OFF_BC2 + 0];
                float r1 = acc[tg][1] + sm[OFF_BC2 + 1];
                float r2 = acc[tg][2] + sm[OFF_BC2 + 2];
                out[(size_t)4*pp + 1] = 1.f / (1.f + expf(-r0));
                out[(size_t)4*pp + 2] = 1.f / (1.f + expf(-r1));
                out[(size_t)4*pp + 3] = 1.f / (1.f + expf(-r2));
            }
        }
        __syncwarp();   // protect H reuse next tile
    }
    #undef A_ADDR
    #undef B_ADDR
}

// ---------------- launch ----------------
extern "C" void kernel_launch(void* const* d_in, const int* in_sizes, int n_in,
                              void* d_out, int out_size) {
    const float* positions  = (const float*)d_in[0];
    const float* directions = (const float*)d_in[1];
    const float* appearance = (const float*)d_in[2];
    const float* centroids  = (const float*)d_in[3];
    const float* Wd1 = (const float*)d_in[4];
    const float* bd1 = (const float*)d_in[5];
    const float* Wd2 = (const float*)d_in[6];
    const float* bd2 = (const float*)d_in[7];
    const float* Wc1 = (const float*)d_in[8];
    const float* bc1 = (const float*)d_in[9];
    const float* Wc2 = (const float*)d_in[10];
    const float* bc2 = (const float*)d_in[11];
    float* out = (float*)d_out;

    int n = in_sizes[0] / 3;
    if (n > N_MAX) n = N_MAX;
    int tpf = (n + PTS_PER_BLOCK - 1) / PTS_PER_BLOCK;

    cudaFuncSetAttribute(k_field, cudaFuncAttributeMaxDynamicSharedMemorySize,
                         SMEM_BYTES);

    void* cptr = nullptr;
    cudaGetSymbolAddress(&cptr, g_counts);
    cudaMemsetAsync(cptr, 0, N_FIELDS * sizeof(int));

    k_assign<<<(n + 255) / 256, 256>>>(positions, centroids, n);
    k_field<<<N_FIELDS * tpf, TILE, SMEM_BYTES>>>(positions, directions, appearance,
                                                  Wd1, bd1, Wd2, bd2, Wc1, bc1,
                                                  Wc2, bc2, out, tpf);
}